// round 17
// baseline (speedup 1.0000x reference)
#include <cuda_runtime.h>
#include <cuda_bf16.h>
#include <cstdint>

// Problem constants
#define NN 4
#define CC 64
#define HH 96
#define WW 96
#define PP (HH * WW)       // 9216
#define OO 1728            // 3*C*9
#define KTOT 2304          // 256*9

// Scratch (__device__ globals per alloc-free rule)
// cat int8 limbs: [n][8 chunk][p][32 ci]
__device__ signed char g_c8h[(size_t)NN * 8 * PP * 32];
__device__ signed char g_c8l[(size_t)NN * 8 * PP * 32];
__device__ unsigned g_w1h[OO * 32];                 // gen_w bf16 pairs, REORDERED o' = dil*576+tap*64+c
__device__ unsigned g_w1l[OO * 32];
__device__ float    g_b1[OO];                       // gen_b reordered to o'
__device__ signed char g_w8h[8 * 9 * 64 * 32];      // fuse_w int8 limbs [chunk][tap][co][ci]
__device__ signed char g_w8l[8 * 9 * 64 * 32];

// ---- bf16 split helpers (fused12 MMA path) ----
static __device__ __forceinline__ void bsplit(float v, unsigned short& h, unsigned short& l) {
    __nv_bfloat16 bh = __float2bfloat16_rn(v);
    float r = v - __bfloat162float(bh);
    __nv_bfloat16 bl = __float2bfloat16_rn(r);
    h = __bfloat16_as_ushort(bh);
    l = __bfloat16_as_ushort(bl);
}
static __device__ __forceinline__ unsigned pk(unsigned short lo, unsigned short hi) {
    return ((unsigned)hi << 16) | lo;
}
// ---- int8 2-limb quantizer: v ~= (h*128 + l) / scale, 15-bit ----
static __device__ __forceinline__ void q15(float v, float scale, signed char& h, signed char& l) {
    int V = __float2int_rn(v * scale);
    V = max(-16320, min(16319, V));
    int Vh = (V + 64) >> 7;
    h = (signed char)Vh;
    l = (signed char)(V - (Vh << 7));
}
static __device__ __forceinline__ uint32_t smem_u32(const void* p) {
    uint32_t a;
    asm("{ .reg .u64 t; cvta.to.shared.u64 t, %1; cvt.u32.u64 %0, t; }" : "=r"(a) : "l"(p));
    return a;
}

// ---- mma/ldmatrix/cp.async ----
static __device__ __forceinline__ void mma16816(
    float& d0, float& d1, float& d2, float& d3,
    uint32_t a0, uint32_t a1, uint32_t a2, uint32_t a3,
    uint32_t b0, uint32_t b1)
{
    asm volatile(
        "mma.sync.aligned.m16n8k16.row.col.f32.bf16.bf16.f32 "
        "{%0,%1,%2,%3}, {%4,%5,%6,%7}, {%8,%9}, {%0,%1,%2,%3};"
        : "+f"(d0), "+f"(d1), "+f"(d2), "+f"(d3)
        : "r"(a0), "r"(a1), "r"(a2), "r"(a3), "r"(b0), "r"(b1));
}
static __device__ __forceinline__ void imma16832(
    int& d0, int& d1, int& d2, int& d3,
    uint32_t a0, uint32_t a1, uint32_t a2, uint32_t a3,
    uint32_t b0, uint32_t b1)
{
    asm volatile(
        "mma.sync.aligned.m16n8k32.row.col.s32.s8.s8.s32 "
        "{%0,%1,%2,%3}, {%4,%5,%6,%7}, {%8,%9}, {%0,%1,%2,%3};"
        : "+r"(d0), "+r"(d1), "+r"(d2), "+r"(d3)
        : "r"(a0), "r"(a1), "r"(a2), "r"(a3), "r"(b0), "r"(b1));
}
static __device__ __forceinline__ void ldsm_x4(
    uint32_t& a0, uint32_t& a1, uint32_t& a2, uint32_t& a3, uint32_t addr)
{
    asm volatile(
        "ldmatrix.sync.aligned.m8n8.x4.shared.b16 {%0,%1,%2,%3}, [%4];"
        : "=r"(a0), "=r"(a1), "=r"(a2), "=r"(a3) : "r"(addr));
}
static __device__ __forceinline__ void cp16(uint32_t dst, const void* src) {
    asm volatile("cp.async.cg.shared.global [%0], [%1], 16;"
                 :: "r"(dst), "l"(src) : "memory");
}
static __device__ __forceinline__ void cp16z(uint32_t dst, const void* src, uint32_t sz) {
    asm volatile("cp.async.cg.shared.global [%0], [%1], 16, %2;"
                 :: "r"(dst), "l"(src), "r"(sz) : "memory");
}

// ============================================================
// Merged prep kernel: 792 CTAs of 256 threads.
//   bx < 216: gen_w -> bf16 pairs (reordered) ; else fuse_w -> int8 limbs
// ============================================================
__global__ void __launch_bounds__(256) prep_all(
    const float* __restrict__ gen_w, const float* __restrict__ gen_b,
    const float* __restrict__ fuse_w)
{
    const int bx = blockIdx.x;
    const int tid = threadIdx.x;

    if (bx < 216) {
        int idx = bx * 256 + tid;
        if (idx < OO * 32) {
            int op = idx >> 5, kp = idx & 31;
            int dil = op / 576;
            int rem = op - dil * 576;
            int tap = rem >> 6;
            int c   = rem & 63;
            int src = dil * 576 + c * 9 + tap;
            unsigned short h0, l0, h1, l1;
            bsplit(__ldg(gen_w + (size_t)src * 64 + 2 * kp), h0, l0);
            bsplit(__ldg(gen_w + (size_t)src * 64 + 2 * kp + 1), h1, l1);
            g_w1h[idx] = pk(h0, h1);
            g_w1l[idx] = pk(l0, l1);
            if (kp == 0) g_b1[op] = __ldg(gen_b + src);
        }
    } else {
        int idx = (bx - 216) * 256 + tid;   // [chunk][tap][co][ci]
        if (idx < 8 * 9 * 64 * 32) {
            int ci  = idx & 31;
            int co  = (idx >> 5) & 63;
            int tap = (idx >> 11) % 9;
            int chunk = idx / (9 * 2048);
            float w = __ldg(fuse_w + (size_t)co * KTOT + (chunk * 32 + ci) * 9 + tap);
            signed char h, l;
            q15(w, 32768.f, h, l);
            g_w8h[idx] = h;
            g_w8l[idx] = l;
        }
    }
}

// ============================================================
// FUSED stage1+2 (R15 MMA path): per CTA = 128 px, 27 chunks.
// grid (72, NN), 256 thr. Epilogue quantizes cat to int8 limbs.
// ============================================================
#define F_AH 0
#define F_AL 18432
#define F_B0 36864
#define F_BSTG 18432
#define F_SM (36864 + 4 * 18432)    // 110592

__global__ void __launch_bounds__(256, 2) fused12(
    const float* __restrict__ x, const float* __restrict__ y)
{
    extern __shared__ __align__(16) char sm[];
    const uint32_t sbase = smem_u32(sm);
    const int n  = blockIdx.y;
    const int p0 = blockIdx.x * 128;
    const int tid = threadIdx.x;
    const int warp = tid >> 5, lane = tid & 31;
    const int g = lane >> 2, t = lane & 3;
    const int wm = warp & 1, wn = warp >> 1;
    const int rsel = lane & 15;
    const int half16 = (lane >> 4) * 16;

    // ---- build A (y^T, bf16 split) in-kernel ----
    {
        float* ystage = (float*)(sm + F_B0);
#pragma unroll
        for (int pass = 0; pass < 8; pass++) {
            int fid = tid + pass * 256;
            int k  = fid >> 5;
            int p4 = (fid & 31) * 4;
            *(float4*)&ystage[k * 132 + p4] =
                *(const float4*)(y + ((size_t)n * 64 + k) * PP + p0 + p4);
        }
        __syncthreads();
#pragma unroll
        for (int pass = 0; pass < 4; pass++) {
            int fid = tid + pass * 256;
            int r = fid >> 3, q = fid & 7;
            unsigned hv[4], lv[4];
#pragma unroll
            for (int i = 0; i < 4; i++) {
                int k = q * 8 + i * 2;
                unsigned short h0, l0, h1, l1;
                bsplit(ystage[k * 132 + r], h0, l0);
                bsplit(ystage[(k + 1) * 132 + r], h1, l1);
                hv[i] = pk(h0, h1);
                lv[i] = pk(l0, l1);
            }
            *(uint4*)(sm + F_AH + r * 144 + q * 16) = make_uint4(hv[0], hv[1], hv[2], hv[3]);
            *(uint4*)(sm + F_AL + r * 144 + q * 16) = make_uint4(lv[0], lv[1], lv[2], lv[3]);
        }
    }

    int hE[8], wE[8];
#pragma unroll
    for (int mi = 0; mi < 4; mi++)
#pragma unroll
        for (int r = 0; r < 2; r++) {
            int px = wm * 64 + mi * 16 + g + 8 * r;
            int p  = p0 + px;
            hE[mi * 2 + r] = p / WW;
            wE[mi * 2 + r] = p - (p / WW) * WW;
        }

    // ---- x passthrough (cat channels 0..63) -> int8 limbs ----
#pragma unroll
    for (int mi = 0; mi < 4; mi++)
#pragma unroll
        for (int r = 0; r < 2; r++) {
            int px = wm * 64 + mi * 16 + g + 8 * r;
#pragma unroll
            for (int ni = 0; ni < 2; ni++) {
                int ce = wn * 16 + ni * 8 + 2 * t;
                float v0 = __ldg(x + ((size_t)n * CC + ce) * PP + p0 + px);
                float v1 = __ldg(x + ((size_t)n * CC + ce + 1) * PP + p0 + px);
                signed char h0, l0, h1, l1;
                q15(v0, 1024.f, h0, l0);
                q15(v1, 1024.f, h1, l1);
                int chunkI = ce >> 5, ci = ce & 31;
                size_t gi = (((size_t)n * 8 + chunkI) * PP + p0 + px) * 32 + ci;
                g_c8h[gi] = h0; g_c8h[gi + 1] = h1;
                g_c8l[gi] = l0; g_c8l[gi + 1] = l1;
            }
        }

    __syncthreads();   // ystage reads done before B prefetch overwrites F_B0

    auto prefetch = [&](int ch) {
        const uint32_t so = F_B0 + (uint32_t)(ch & 3) * F_BSTG;
#pragma unroll
        for (int ps = 0; ps < 2; ps++) {
            int fid = tid + ps * 256;
            int o = fid >> 3, q = fid & 7;
            size_t gi = ((size_t)(ch * 64 + o)) * 32 + q * 4;
            uint32_t doff = sbase + so + (uint32_t)(o * 144 + q * 16);
            cp16(doff,        g_w1h + gi);
            cp16(doff + 9216, g_w1l + gi);
        }
        asm volatile("cp.async.commit_group;" ::: "memory");
    };

    prefetch(0);
    prefetch(1);

    const float* xn = x + (size_t)n * CC * PP;

#pragma unroll 1
    for (int dil = 0; dil < 3; dil++) {
        float acc[4][2][4];
#pragma unroll
        for (int i = 0; i < 4; i++)
#pragma unroll
            for (int j = 0; j < 2; j++)
#pragma unroll
                for (int q = 0; q < 4; q++) acc[i][j][q] = 0.f;

        const int dd = 2 * dil + 1;

#pragma unroll 1
        for (int tap = 0; tap < 9; tap++) {
            const int ch = dil * 9 + tap;
            const uint32_t so = F_B0 + (uint32_t)(ch & 3) * F_BSTG;
            if (ch + 2 < 27) {
                prefetch(ch + 2);
                asm volatile("cp.async.wait_group 2;" ::: "memory");
            } else if (ch + 2 == 27) {
                asm volatile("cp.async.wait_group 1;" ::: "memory");
            } else {
                asm volatile("cp.async.wait_group 0;" ::: "memory");
            }
            __syncthreads();

            float d[4][2][4];
#pragma unroll
            for (int i = 0; i < 4; i++)
#pragma unroll
                for (int j = 0; j < 2; j++)
#pragma unroll
                    for (int q = 0; q < 4; q++) d[i][j][q] = 0.f;

            const char* BH = sm + so;
            const char* BL = sm + so + 9216;
#pragma unroll
            for (int ks = 0; ks < 4; ks++) {
                const int kb = ks * 32;
                uint32_t aH[4][4], aL[4][4], bH[2][2], bL[2][2];
#pragma unroll
                for (int mi = 0; mi < 4; mi++) {
                    ldsm_x4(aH[mi][0], aH[mi][1], aH[mi][2], aH[mi][3],
                            sbase + F_AH + (wm * 64 + mi * 16 + rsel) * 144 + kb + half16);
                    ldsm_x4(aL[mi][0], aL[mi][1], aL[mi][2], aL[mi][3],
                            sbase + F_AL + (wm * 64 + mi * 16 + rsel) * 144 + kb + half16);
                }
#pragma unroll
                for (int ni = 0; ni < 2; ni++) {
                    const char* pH = BH + (wn * 16 + ni * 8 + g) * 144 + kb + t * 4;
                    const char* pL = BL + (wn * 16 + ni * 8 + g) * 144 + kb + t * 4;
                    bH[ni][0] = *(const uint32_t*)pH;
                    bH[ni][1] = *(const uint32_t*)(pH + 16);
                    bL[ni][0] = *(const uint32_t*)pL;
                    bL[ni][1] = *(const uint32_t*)(pL + 16);
                }
#pragma unroll
                for (int s = 0; s < 3; s++)
#pragma unroll
                    for (int mi = 0; mi < 4; mi++)
#pragma unroll
                        for (int ni = 0; ni < 2; ni++) {
                            const uint32_t* a = (s < 2) ? aH[mi] : aL[mi];
                            const uint32_t* b = (s == 1) ? bL[ni] : bH[ni];
                            mma16816(d[mi][ni][0], d[mi][ni][1], d[mi][ni][2], d[mi][ni][3],
                                     a[0], a[1], a[2], a[3], b[0], b[1]);
                        }
            }

            const int did = (tap / 3 - 1) * dd;
            const int djd = (tap % 3 - 1) * dd;
            const int soff = did * WW + djd;
            float2 bias[2];
#pragma unroll
            for (int ni = 0; ni < 2; ni++)
                bias[ni] = __ldg((const float2*)(g_b1 + ch * 64 + wn * 16 + ni * 8 + 2 * t));

#pragma unroll
            for (int mi = 0; mi < 4; mi++)
#pragma unroll
                for (int r = 0; r < 2; r++) {
                    const int e = mi * 2 + r;
                    const bool vok = ((unsigned)(hE[e] + did) < (unsigned)HH) &&
                                     ((unsigned)(wE[e] + djd) < (unsigned)WW);
                    const int px = wm * 64 + mi * 16 + g + 8 * r;
                    const int pa = p0 + px + soff;
#pragma unroll
                    for (int ni = 0; ni < 2; ni++) {
                        const int ce = wn * 16 + ni * 8 + 2 * t;
                        float x0 = 0.f, x1 = 0.f;
                        if (vok) {
                            x0 = __ldg(xn + (size_t)ce * PP + pa);
                            x1 = __ldg(xn + (size_t)(ce + 1) * PP + pa);
                        }
                        acc[mi][ni][r * 2 + 0] += (d[mi][ni][r * 2 + 0] + bias[ni].x) * x0;
                        acc[mi][ni][r * 2 + 1] += (d[mi][ni][r * 2 + 1] + bias[ni].y) * x1;
                    }
                }
        }

        // ---- write cat section (dil+1) as int8 limbs ----
#pragma unroll
        for (int mi = 0; mi < 4; mi++)
#pragma unroll
            for (int r = 0; r < 2; r++) {
                int px = wm * 64 + mi * 16 + g + 8 * r;
#pragma unroll
                for (int ni = 0; ni < 2; ni++) {
                    signed char h0, l0, h1, l1;
                    q15(acc[mi][ni][r * 2 + 0], 1024.f, h0, l0);
                    q15(acc[mi][ni][r * 2 + 1], 1024.f, h1, l1);
                    int cE = (dil + 1) * 64 + wn * 16 + ni * 8 + 2 * t;
                    int chunkI = cE >> 5, ci = cE & 31;
                    size_t gi = (((size_t)n * 8 + chunkI) * PP + p0 + px) * 32 + ci;
                    g_c8h[gi] = h0; g_c8h[gi + 1] = h1;
                    g_c8l[gi] = l0; g_c8l[gi + 1] = l1;
                }
            }
    }
}

// ============================================================
// Stage 3 (int8 m16n8k32): CTA = 2 rows x 32 co, 256 thr, grid (48,2,4).
// 8 chunks of 32 ci; 4 IMMA terms per k32 into 3 int32 accumulator sets.
// A smem [4 dy][100 px][48B pad] per limb; B [9 tap][32 co][48B pad].
// 3 buffers, 1-deep prefetch, one sync per chunk.
// ============================================================
#define S3_AL_O  19200
#define S3_BH_O  38400
#define S3_BL_O  52224
#define S3_STG   66048
#define S3_SM    (3 * S3_STG)     // 198144

__global__ void __launch_bounds__(256) stage3_mma(
    const float* __restrict__ fuse_b, float* __restrict__ out)
{
    extern __shared__ __align__(16) char sm[];
    const uint32_t sbase = smem_u32(sm);
    const int h0  = blockIdx.x * 2;
    const int coh = blockIdx.y;
    const int n   = blockIdx.z;
    const int tid = threadIdx.x;
    const int warp = tid >> 5, lane = tid & 31;
    const int g = lane >> 2, t = lane & 3;
    const int r  = warp & 1;
    const int wm = (warp >> 1) & 1;
    const int wn = warp >> 2;
    const int rsel = lane & 15;
    const int half16 = (lane >> 4) * 16;

    auto prefetch = [&](int chunk, uint32_t so) {
        // A: 4 dy x 98 u positions, 32B (2x16) per limb, zero-fill guards
#pragma unroll
        for (int ps = 0; ps < 2; ps++) {
            int fid = tid + ps * 256;
            if (fid < 392) {
                int dy = fid / 98;
                int u  = fid - dy * 98;
                int hh = h0 + dy - 1;
                int w  = u - 1;
                bool ok = ((unsigned)hh < (unsigned)HH) && ((unsigned)w < (unsigned)WW);
                uint32_t sz = ok ? 16u : 0u;
                size_t gi = (((size_t)n * 8 + chunk) * PP + (ok ? (hh * WW + w) : 0)) * 32;
                uint32_t doff = sbase + so + (uint32_t)((dy * 100 + u) * 48);
                cp16z(doff,                g_c8h + gi,      sz);
                cp16z(doff + 16,           g_c8h + gi + 16, sz);
                cp16z(doff + S3_AL_O,      g_c8l + gi,      sz);
                cp16z(doff + S3_AL_O + 16, g_c8l + gi + 16, sz);
            }
        }
        // B: 9 tap x 32 co x 32B per limb
#pragma unroll
        for (int ps = 0; ps < 3; ps++) {
            int fid = tid + ps * 256;
            if (fid < 576) {
                int row  = fid >> 1;            // tap*32 + coL
                int half = fid & 1;
                int tap  = row >> 5;
                int coL  = row & 31;
                size_t gi = (((size_t)chunk * 9 + tap) * 64 + coh * 32 + coL) * 32 + half * 16;
                uint32_t doff = sbase + so + S3_BH_O
                                + (uint32_t)((tap * 32 + coL) * 48 + half * 16);
                cp16(doff,                       g_w8h + gi);
                cp16(doff + (S3_BL_O - S3_BH_O), g_w8l + gi);
            }
        }
        asm volatile("cp.async.commit_group;" ::: "memory");
    };

    // 3 int32 accumulator sets: 0 = HH (scale 2^14), 1 = HL+LH (2^7), 2 = LL (1)
    int d[3][3][2][4];
#pragma unroll
    for (int s = 0; s < 3; s++)
#pragma unroll
        for (int i = 0; i < 3; i++)
#pragma unroll
            for (int j = 0; j < 2; j++)
#pragma unroll
                for (int q = 0; q < 4; q++) d[s][i][j][q] = 0;

    prefetch(0, 0);

    int cur = 0;
#pragma unroll 1
    for (int chunk = 0; chunk < 8; chunk++) {
        const uint32_t so = (uint32_t)cur * S3_STG;
        int nxt = (cur == 2) ? 0 : cur + 1;
        if (chunk + 1 < 8) {
            prefetch(chunk + 1, (uint32_t)nxt * S3_STG);
            asm volatile("cp.async.wait_group 1;" ::: "memory");
        } else {
            asm volatile("cp.async.wait_group 0;" ::: "memory");
        }
        __syncthreads();

        const uint32_t AbH = sbase + so + rsel * 48 + half16;
        const uint32_t AbL = AbH + S3_AL_O;
        const char* BpH = sm + so + S3_BH_O;
        const char* BpL = sm + so + S3_BL_O;

#pragma unroll
        for (int tap = 0; tap < 9; tap++) {
            const int dy = tap / 3, dx = tap % 3;
            uint32_t bH[2][2], bL[2][2];
#pragma unroll
            for (int ni = 0; ni < 2; ni++) {
                int coL = wn * 16 + ni * 8 + g;
                const char* pH = BpH + (tap * 32 + coL) * 48 + 4 * t;
                const char* pL = BpL + (tap * 32 + coL) * 48 + 4 * t;
                bH[ni][0] = *(const uint32_t*)pH;
                bH[ni][1] = *(const uint32_t*)(pH + 16);
                bL[ni][0] = *(const uint32_t*)pL;
                bL[ni][1] = *(const uint32_t*)(pL + 16);
            }
            uint32_t aH[3][4], aL[3][4];
#pragma unroll
            for (int mi = 0; mi < 3; mi++) {
                int px0 = wm * 48 + mi * 16 + dx;
                int off = ((r + dy) * 100 + px0) * 48;
                ldsm_x4(aH[mi][0], aH[mi][1], aH[mi][2], aH[mi][3], AbH + off);
                ldsm_x4(aL[mi][0], aL[mi][1], aL[mi][2], aL[mi][3], AbL + off);
            }
            // 24 IMMAs: HH -> d0, HL -> d1, LH -> d1, LL -> d2
#pragma unroll
            for (int mi = 0; mi < 3; mi++)
#pragma unroll
                for (int ni = 0; ni < 2; ni++)
                    imma16832(d[0][mi][ni][0], d[0][mi][ni][1], d[0][mi][ni][2], d[0][mi][ni][3],
                              aH[mi][0], aH[mi][1], aH[mi][2], aH[mi][3], bH[ni][0], bH[ni][1]);
#pragma unroll
            for (int mi = 0; mi < 3; mi++)
#pragma unroll
                for (int ni = 0; ni < 2; ni++)
                    imma16832(d[1][mi][ni][0], d[1][mi][ni][1], d[1][mi][ni][2], d[1][mi][ni][3],
                              aH[mi][0], aH[mi][1], aH[mi][2], aH[mi][3], bL[ni][0], bL[ni][1]);
#pragma unroll
            for (int mi = 0; mi < 3; mi++)
#pragma unroll
                for (int ni = 0; ni < 2; ni++)
                    imma16832(d[1][mi][ni][0], d[1][mi][ni][1], d[1][mi][ni][2], d[1][mi][ni][3],
                              aL[mi][0], aL[mi][1], aL[mi][2], aL[mi][3], bH[ni][0], bH[ni][1]);
#pragma unroll
            for (int mi = 0; mi < 3; mi++)
#pragma unroll
                for (int ni = 0; ni < 2; ni++)
                    imma16832(d[2][mi][ni][0], d[2][mi][ni][1], d[2][mi][ni][2], d[2][mi][ni][3],
                              aL[mi][0], aL[mi][1], aL[mi][2], aL[mi][3], bL[ni][0], bL[ni][1]);
        }
        cur = nxt;
    }

    const int h = h0 + r;
#pragma unroll
    for (int mi = 0; mi < 3; mi++) {
        int pxcol = wm * 48 + mi * 16 + g;
#pragma unroll
        for (int ni = 0; ni < 2; ni++) {
            int co = coh * 32 + wn * 16 + ni * 8 + 2 * t;
            float b0v = __ldg(fuse_b + co);
            float b1v = __ldg(fuse_b + co + 1);
            float* r0 = out + ((size_t)n * CC + co) * PP + h * WW;
            float* r1 = r0 + PP;
#pragma unroll
            for (int q = 0; q < 4; q++) {
                float v = (float)d[0][mi][ni][q] * 0x1p-11f
                        + (float)d[1][mi][ni][q] * 0x1p-18f
                        + (float)d[2][mi][ni][q] * 0x1p-25f;
                float bv = (q & 1) ? b1v : b0v;
                float* dst = (q & 1) ? r1 : r0;
                dst[pxcol + (q >> 1) * 8] = v + bv;
            }
        }
    }
}

// ============================================================
extern "C" void kernel_launch(void* const* d_in, const int* in_sizes, int n_in,
                              void* d_out, int out_size)
{
    (void)in_sizes; (void)n_in; (void)out_size;
    const float* x      = (const float*)d_in[0];
    const float* y      = (const float*)d_in[1];
    const float* gen_w  = (const float*)d_in[2];
    const float* gen_b  = (const float*)d_in[3];
    const float* fuse_w = (const float*)d_in[4];
    const float* fuse_b = (const float*)d_in[5];
    float* out = (float*)d_out;

    cudaFuncSetAttribute(fused12, cudaFuncAttributeMaxDynamicSharedMemorySize, F_SM);
    cudaFuncSetAttribute(stage3_mma, cudaFuncAttributeMaxDynamicSharedMemorySize, S3_SM);

    prep_all<<<792, 256>>>(gen_w, gen_b, fuse_w);

    fused12<<<dim3(PP / 128, NN), 256, F_SM>>>(x, y);

    stage3_mma<<<dim3(HH / 2, 2, NN), 256, S3_SM>>>(fuse_b, out);
}